// round 3
// baseline (speedup 1.0000x reference)
#include <cuda_runtime.h>
#include <math.h>

// Problem constants
#define BB 2
#define SS 2048
#define DD 1024
#define HH 16
#define HD 64

// Scratch (allocation-free rule: __device__ globals)
// g_qkv layout: [3][B][H][S][HD]
__device__ float g_qkv[(size_t)3 * BB * HH * SS * HD];   // ~50 MB
// g_attn layout: [B][S][D]  (attention output, already transposed back)
__device__ float g_attn[(size_t)BB * SS * DD];           // ~16 MB

#define HEAD_ELEMS ((size_t)SS * HD)
#define QKV_ONE    ((size_t)BB * HH * SS * HD)

// ---------------------------------------------------------------------------
// Kernel 1: QKV GEMM.  qkv[m, n] = x[m, :] . w_qkv[n, :] + b_qkv[n]
// M = B*S = 4096, N = 3*D = 3072, K = D = 1024.
// Epilogue scatters into g_qkv[which][b][h][s][d].
// 64x64 tile, BK=16, 256 threads, 4x4 micro-tile per thread.
// ---------------------------------------------------------------------------
__global__ __launch_bounds__(256) void qkv_gemm_kernel(
    const float* __restrict__ x, const float* __restrict__ w,
    const float* __restrict__ bias)
{
    __shared__ float As[64][17];
    __shared__ float Ws[64][17];

    const int tid = threadIdx.x;
    const int tx = tid & 15, ty = tid >> 4;
    const int m0 = blockIdx.y << 6;
    const int n0 = blockIdx.x << 6;
    const int lrow = tid >> 2;          // 0..63
    const int lcol = (tid & 3) << 2;    // 0,4,8,12

    float acc[4][4] = {};

    const float* aP = x + (size_t)(m0 + lrow) * DD + lcol;
    const float* wP = w + (size_t)(n0 + lrow) * DD + lcol;

    for (int k0 = 0; k0 < DD; k0 += 16) {
        float4 av = *(const float4*)(aP + k0);
        float4 wv = *(const float4*)(wP + k0);
        As[lrow][lcol + 0] = av.x; As[lrow][lcol + 1] = av.y;
        As[lrow][lcol + 2] = av.z; As[lrow][lcol + 3] = av.w;
        Ws[lrow][lcol + 0] = wv.x; Ws[lrow][lcol + 1] = wv.y;
        Ws[lrow][lcol + 2] = wv.z; Ws[lrow][lcol + 3] = wv.w;
        __syncthreads();

        #pragma unroll
        for (int k = 0; k < 16; ++k) {
            float a[4], b[4];
            #pragma unroll
            for (int i = 0; i < 4; ++i) a[i] = As[(ty << 2) + i][k];
            #pragma unroll
            for (int j = 0; j < 4; ++j) b[j] = Ws[(tx << 2) + j][k];
            #pragma unroll
            for (int i = 0; i < 4; ++i)
                #pragma unroll
                for (int j = 0; j < 4; ++j)
                    acc[i][j] += a[i] * b[j];
        }
        __syncthreads();
    }

    #pragma unroll
    for (int i = 0; i < 4; ++i) {
        const int m = m0 + (ty << 2) + i;
        const int b = m >> 11;            // batch
        const int s = m & 2047;           // seq pos
        #pragma unroll
        for (int j = 0; j < 4; ++j) {
            const int n = n0 + (tx << 2) + j;
            const float v = acc[i][j] + bias[n];
            const int which = n >> 10;
            const int r = n & 1023;
            const int h = r >> 6;
            const int d = r & 63;
            g_qkv[(((((size_t)which * BB + b) * HH + h) * SS + s) * HD) + d] = v;
        }
    }
}

// ---------------------------------------------------------------------------
// Kernel 2: flash attention (fp32).
// grid = (S/64, B*H); block = 256 threads (16x16 layout, 4x4 micro-tiles).
// Online softmax; P staged through smem for the PV product.
// Output written to g_attn[b][s][h*64+d].
// ---------------------------------------------------------------------------
#define QPAD 65
#define FLASH_SMEM (4 * 64 * QPAD * (int)sizeof(float))

__global__ __launch_bounds__(256) void flash_attn_kernel()
{
    extern __shared__ float sm[];
    float* Qs = sm;
    float* Ks = sm + 1 * 64 * QPAD;
    float* Vs = sm + 2 * 64 * QPAD;
    float* Ps = sm + 3 * 64 * QPAD;

    const int tid = threadIdx.x;
    const int tx = tid & 15, ty = tid >> 4;
    const int q0 = blockIdx.x << 6;
    const int bh = blockIdx.y;
    const int b = bh >> 4, h = bh & 15;

    const size_t head_off = (size_t)(b * HH + h) * HEAD_ELEMS;
    const float* Qg = g_qkv + head_off;
    const float* Kg = g_qkv + QKV_ONE + head_off;
    const float* Vg = g_qkv + 2 * QKV_ONE + head_off;

    // Load Q tile [64][64] (float4, coalesced)
    #pragma unroll
    for (int i = 0; i < 4; ++i) {
        const int e = tid + i * 256;            // float4 index
        const int row = e >> 4;
        const int col = (e & 15) << 2;
        float4 v = *(const float4*)(Qg + (size_t)(q0 + row) * HD + col);
        float* q = &Qs[row * QPAD + col];
        q[0] = v.x; q[1] = v.y; q[2] = v.z; q[3] = v.w;
    }

    float acc[4][4] = {};
    float mrow[4], lrow[4];
    #pragma unroll
    for (int i = 0; i < 4; ++i) { mrow[i] = -1e30f; lrow[i] = 0.0f; }

    const float scale = 0.125f;   // 1/sqrt(64)

    for (int kt = 0; kt < SS / 64; ++kt) {
        __syncthreads();   // protect Ks/Vs/Ps reuse (and Q load on first iter)

        // Load K and V tiles
        #pragma unroll
        for (int i = 0; i < 4; ++i) {
            const int e = tid + i * 256;
            const int row = e >> 4;
            const int col = (e & 15) << 2;
            const size_t g = (size_t)(kt * 64 + row) * HD + col;
            float4 kv = *(const float4*)(Kg + g);
            float4 vv = *(const float4*)(Vg + g);
            float* kp = &Ks[row * QPAD + col];
            kp[0] = kv.x; kp[1] = kv.y; kp[2] = kv.z; kp[3] = kv.w;
            float* vp = &Vs[row * QPAD + col];
            vp[0] = vv.x; vp[1] = vv.y; vp[2] = vv.z; vp[3] = vv.w;
        }
        __syncthreads();

        // S = Q @ K^T  (per-thread 4x4)
        float sc[4][4] = {};
        #pragma unroll 8
        for (int d = 0; d < 64; ++d) {
            float a[4], kk[4];
            #pragma unroll
            for (int i = 0; i < 4; ++i) a[i] = Qs[((ty << 2) + i) * QPAD + d];
            #pragma unroll
            for (int j = 0; j < 4; ++j) kk[j] = Ks[((tx << 2) + j) * QPAD + d];
            #pragma unroll
            for (int i = 0; i < 4; ++i)
                #pragma unroll
                for (int j = 0; j < 4; ++j)
                    sc[i][j] += a[i] * kk[j];
        }

        // Online softmax per q-row; row spread over 16 lanes (tx)
        #pragma unroll
        for (int i = 0; i < 4; ++i) {
            float mx = -1e30f;
            #pragma unroll
            for (int j = 0; j < 4; ++j) {
                sc[i][j] *= scale;
                mx = fmaxf(mx, sc[i][j]);
            }
            #pragma unroll
            for (int msk = 1; msk < 16; msk <<= 1)
                mx = fmaxf(mx, __shfl_xor_sync(0xffffffffu, mx, msk));

            const float mnew = fmaxf(mrow[i], mx);
            const float corr = __expf(mrow[i] - mnew);
            mrow[i] = mnew;

            float rs = 0.0f;
            #pragma unroll
            for (int j = 0; j < 4; ++j) {
                sc[i][j] = __expf(sc[i][j] - mnew);
                rs += sc[i][j];
            }
            #pragma unroll
            for (int msk = 1; msk < 16; msk <<= 1)
                rs += __shfl_xor_sync(0xffffffffu, rs, msk);

            lrow[i] = lrow[i] * corr + rs;
            #pragma unroll
            for (int j = 0; j < 4; ++j) acc[i][j] *= corr;
            #pragma unroll
            for (int j = 0; j < 4; ++j)
                Ps[((ty << 2) + i) * QPAD + (tx << 2) + j] = sc[i][j];
        }
        __syncthreads();

        // O += P @ V   (acc columns now index head-dim via tx)
        #pragma unroll 8
        for (int k = 0; k < 64; ++k) {
            float p[4], vv[4];
            #pragma unroll
            for (int i = 0; i < 4; ++i) p[i] = Ps[((ty << 2) + i) * QPAD + k];
            #pragma unroll
            for (int j = 0; j < 4; ++j) vv[j] = Vs[k * QPAD + (tx << 2) + j];
            #pragma unroll
            for (int i = 0; i < 4; ++i)
                #pragma unroll
                for (int j = 0; j < 4; ++j)
                    acc[i][j] += p[i] * vv[j];
        }
    }

    // Epilogue: O /= l, write to [B,S,H*hd]
    #pragma unroll
    for (int i = 0; i < 4; ++i) {
        const float inv = 1.0f / lrow[i];
        const int s = q0 + (ty << 2) + i;
        #pragma unroll
        for (int j = 0; j < 4; ++j) {
            g_attn[((size_t)b * SS + s) * DD + h * HD + (tx << 2) + j] =
                acc[i][j] * inv;
        }
    }
}

// ---------------------------------------------------------------------------
// Kernel 3: output projection.  out[m, n] = attn[m, :] . w_proj[n, :] + b[n]
// M = 4096, N = 1024, K = 1024.
// ---------------------------------------------------------------------------
__global__ __launch_bounds__(256) void proj_gemm_kernel(
    const float* __restrict__ w, const float* __restrict__ bias,
    float* __restrict__ out)
{
    __shared__ float As[64][17];
    __shared__ float Ws[64][17];

    const int tid = threadIdx.x;
    const int tx = tid & 15, ty = tid >> 4;
    const int m0 = blockIdx.y << 6;
    const int n0 = blockIdx.x << 6;
    const int lrow = tid >> 2;
    const int lcol = (tid & 3) << 2;

    float acc[4][4] = {};

    const float* aP = g_attn + (size_t)(m0 + lrow) * DD + lcol;
    const float* wP = w + (size_t)(n0 + lrow) * DD + lcol;

    for (int k0 = 0; k0 < DD; k0 += 16) {
        float4 av = *(const float4*)(aP + k0);
        float4 wv = *(const float4*)(wP + k0);
        As[lrow][lcol + 0] = av.x; As[lrow][lcol + 1] = av.y;
        As[lrow][lcol + 2] = av.z; As[lrow][lcol + 3] = av.w;
        Ws[lrow][lcol + 0] = wv.x; Ws[lrow][lcol + 1] = wv.y;
        Ws[lrow][lcol + 2] = wv.z; Ws[lrow][lcol + 3] = wv.w;
        __syncthreads();

        #pragma unroll
        for (int k = 0; k < 16; ++k) {
            float a[4], b[4];
            #pragma unroll
            for (int i = 0; i < 4; ++i) a[i] = As[(ty << 2) + i][k];
            #pragma unroll
            for (int j = 0; j < 4; ++j) b[j] = Ws[(tx << 2) + j][k];
            #pragma unroll
            for (int i = 0; i < 4; ++i)
                #pragma unroll
                for (int j = 0; j < 4; ++j)
                    acc[i][j] += a[i] * b[j];
        }
        __syncthreads();
    }

    #pragma unroll
    for (int i = 0; i < 4; ++i) {
        const int m = m0 + (ty << 2) + i;
        #pragma unroll
        for (int j = 0; j < 4; ++j) {
            const int n = n0 + (tx << 2) + j;
            out[(size_t)m * DD + n] = acc[i][j] + bias[n];
        }
    }
}

// ---------------------------------------------------------------------------
// Launch
// ---------------------------------------------------------------------------
extern "C" void kernel_launch(void* const* d_in, const int* in_sizes, int n_in,
                              void* d_out, int out_size)
{
    (void)in_sizes; (void)n_in; (void)out_size;
    const float* x      = (const float*)d_in[0];
    const float* w_qkv  = (const float*)d_in[1];
    const float* b_qkv  = (const float*)d_in[2];
    const float* w_proj = (const float*)d_in[3];
    const float* b_proj = (const float*)d_in[4];
    float* out = (float*)d_out;

    // Dynamic smem opt-in for the flash kernel (66560 B > 48 KB default).
    // Idempotent host-side attribute set; adds no graph nodes.
    cudaFuncSetAttribute(flash_attn_kernel,
                         cudaFuncAttributeMaxDynamicSharedMemorySize,
                         FLASH_SMEM);

    // 1) QKV projection: M=4096, N=3072 -> grid (48, 64)
    qkv_gemm_kernel<<<dim3(3 * DD / 64, BB * SS / 64), 256>>>(x, w_qkv, b_qkv);

    // 2) Flash attention: grid (S/64, B*H) = (32, 32)
    flash_attn_kernel<<<dim3(SS / 64, BB * HH), 256, FLASH_SMEM>>>();

    // 3) Output projection: M=4096, N=1024 -> grid (16, 64)
    proj_gemm_kernel<<<dim3(DD / 64, BB * SS / 64), 256>>>(w_proj, b_proj, out);
}

// round 9
// speedup vs baseline: 3.2982x; 3.2982x over previous
#include <cuda_runtime.h>
#include <cstdint>
#include <math.h>

// Problem constants
#define BB 2
#define SS 2048
#define DD 1024
#define HH 16
#define HD 64

// Scratch (allocation-free rule: __device__ globals)
__device__ float g_qkv[(size_t)3 * BB * HH * SS * HD];   // [3][B][H][S][HD]
__device__ float g_attn[(size_t)BB * SS * DD];           // [B][S][D]

#define HEAD_ELEMS ((size_t)SS * HD)
#define QKV_ONE    ((size_t)BB * HH * SS * HD)

// ===========================================================================
// TF32 helpers
// ===========================================================================
// Round-to-nearest fp32 -> tf32 (still a valid fp32 bit pattern).
// Removes the coherent truncation bias of feeding raw fp32 to mma.sync.
__device__ __forceinline__ float tf32_rna(float x) {
    uint32_t u;
    asm("cvt.rna.tf32.f32 %0, %1;" : "=r"(u) : "f"(x));
    return __uint_as_float(u);
}
__device__ __forceinline__ float4 tf32_rna4(float4 v) {
    v.x = tf32_rna(v.x); v.y = tf32_rna(v.y);
    v.z = tf32_rna(v.z); v.w = tf32_rna(v.w);
    return v;
}

// TF32 mma.sync (m16n8k8): A row-major, B col-major, fp32 accum.
// Fragment layout (g = lane>>2, t4 = lane&3):
//   A: a0=(g,t4) a1=(g+8,t4) a2=(g,t4+4) a3=(g+8,t4+4)
//   B: b0=(k=t4,n=g) b1=(k=t4+4,n=g)
//   C: c0=(g,2t4) c1=(g,2t4+1) c2=(g+8,2t4) c3=(g+8,2t4+1)
__device__ __forceinline__ void mma_tf32(float* d, const uint32_t* a,
                                         const uint32_t* b) {
    asm volatile(
        "mma.sync.aligned.m16n8k8.row.col.f32.tf32.tf32.f32 "
        "{%0,%1,%2,%3}, {%4,%5,%6,%7}, {%8,%9}, {%0,%1,%2,%3};"
        : "+f"(d[0]), "+f"(d[1]), "+f"(d[2]), "+f"(d[3])
        : "r"(a[0]), "r"(a[1]), "r"(a[2]), "r"(a[3]), "r"(b[0]), "r"(b[1]));
}

// ===========================================================================
// GEMM: C[128x128] = A[128xK] . W[128xK]^T + bias.  K = 1024.
// 256 threads, 8 warps in 2(M) x 4(N); warp tile 64x32 (4x4 m16n8 tiles).
// MODE 0: scatter epilogue into g_qkv.  MODE 1: row-major out.
// ===========================================================================
#define GEMM_K 1024
#define ASTR   36     // 32 + 4 pad floats; conflict-free quad frag loads

template <int MODE>
__global__ __launch_bounds__(256, 2) void tc_gemm_kernel(
    const float* __restrict__ A, const float* __restrict__ W,
    const float* __restrict__ bias, float* __restrict__ out)
{
    __shared__ float As[128 * ASTR];
    __shared__ float Bs[128 * ASTR];

    const int tid = threadIdx.x;
    const int wid = tid >> 5;
    const int lane = tid & 31;
    const int g = lane >> 2;
    const int t4 = lane & 3;
    const int warpM = wid >> 2;       // 0..1
    const int warpN = wid & 3;        // 0..3
    const int m0 = blockIdx.y << 7;
    const int n0 = blockIdx.x << 7;

    const float* aBase = A + (size_t)m0 * GEMM_K;
    const float* wBase = W + (size_t)n0 * GEMM_K;

    float acc[4][4][4] = {};

    for (int s = 0; s < GEMM_K / 32; ++s) {
        const int k0 = s * 32;
        // Stage A/B tiles: 128 rows x 32 floats each (rounded to tf32)
        #pragma unroll
        for (int i = 0; i < 4; ++i) {
            const int e = tid + i * 256;
            const int row = e >> 3;
            const int c4 = e & 7;
            *(float4*)&As[row * ASTR + c4 * 4] = tf32_rna4(
                *(const float4*)(aBase + (size_t)row * GEMM_K + k0 + c4 * 4));
            *(float4*)&Bs[row * ASTR + c4 * 4] = tf32_rna4(
                *(const float4*)(wBase + (size_t)row * GEMM_K + k0 + c4 * 4));
        }
        __syncthreads();

        #pragma unroll
        for (int kc = 0; kc < 4; ++kc) {
            uint32_t afr[4][4], bfr[4][2];
            #pragma unroll
            for (int mt = 0; mt < 4; ++mt) {
                const float* p = &As[(warpM * 64 + mt * 16 + g) * ASTR + kc * 8 + t4];
                afr[mt][0] = __float_as_uint(p[0]);
                afr[mt][1] = __float_as_uint(p[8 * ASTR]);
                afr[mt][2] = __float_as_uint(p[4]);
                afr[mt][3] = __float_as_uint(p[8 * ASTR + 4]);
            }
            #pragma unroll
            for (int nt = 0; nt < 4; ++nt) {
                const float* p = &Bs[(warpN * 32 + nt * 8 + g) * ASTR + kc * 8 + t4];
                bfr[nt][0] = __float_as_uint(p[0]);
                bfr[nt][1] = __float_as_uint(p[4]);
            }
            #pragma unroll
            for (int mt = 0; mt < 4; ++mt)
                #pragma unroll
                for (int nt = 0; nt < 4; ++nt)
                    mma_tf32(acc[mt][nt], afr[mt], bfr[nt]);
        }
        __syncthreads();
    }

    // Epilogue
    #pragma unroll
    for (int mt = 0; mt < 4; ++mt) {
        const int r0 = m0 + warpM * 64 + mt * 16 + g;
        const int r1 = r0 + 8;
        #pragma unroll
        for (int nt = 0; nt < 4; ++nt) {
            const int n = n0 + warpN * 32 + nt * 8 + t4 * 2;
            const float bn0 = bias[n], bn1 = bias[n + 1];
            const float v00 = acc[mt][nt][0] + bn0;
            const float v01 = acc[mt][nt][1] + bn1;
            const float v10 = acc[mt][nt][2] + bn0;
            const float v11 = acc[mt][nt][3] + bn1;
            if (MODE == 0) {
                const int which = n >> 10;
                const int rn = n & 1023;
                const int h = rn >> 6;
                const int d = rn & 63;
                const int b = r0 >> 11;           // r0, r1 same batch
                const size_t base =
                    ((((size_t)which * BB + b) * HH + h) * SS);
                size_t i0 = (base + (r0 & 2047)) * HD + d;
                size_t i1 = (base + (r1 & 2047)) * HD + d;
                g_qkv[i0] = v00; g_qkv[i0 + 1] = v01;
                g_qkv[i1] = v10; g_qkv[i1 + 1] = v11;
            } else {
                out[(size_t)r0 * DD + n] = v00;
                out[(size_t)r0 * DD + n + 1] = v01;
                out[(size_t)r1 * DD + n] = v10;
                out[(size_t)r1 * DD + n + 1] = v11;
            }
        }
    }
}

// ===========================================================================
// Flash attention on mma.sync TF32.
// 128 queries x 64 keys per tile. 256 threads; warp w owns q-rows w*16..+15.
// Q fragments live in registers; the Q smem region is reused as the P buffer
// (P must round-trip smem: tf32 C-frag and A-frag layouts differ).
// grid = (S/128, B*H) = (16, 32).
// ===========================================================================
#define FSTR 68
#define FLASH_SMEM ((128 + 64 + 64) * FSTR * (int)sizeof(float))   // 69632

__global__ __launch_bounds__(256, 2) void flash_attn_kernel()
{
    extern __shared__ float sm[];
    float* QP = sm;                       // [128][FSTR]  Q, then P
    float* Ks = sm + 128 * FSTR;          // [64][FSTR]
    float* Vs = Ks + 64 * FSTR;           // [64][FSTR]

    const int tid = threadIdx.x;
    const int wid = tid >> 5;
    const int lane = tid & 31;
    const int g = lane >> 2;
    const int t4 = lane & 3;
    const int q0 = blockIdx.x << 7;
    const int bh = blockIdx.y;
    const int b = bh >> 4, h = bh & 15;

    const size_t head_off = (size_t)(b * HH + h) * HEAD_ELEMS;
    const float* Qg = g_qkv + head_off;
    const float* Kg = g_qkv + QKV_ONE + head_off;
    const float* Vg = g_qkv + 2 * QKV_ONE + head_off;

    // Stage Q tile [128][64] (rounded to tf32)
    #pragma unroll
    for (int i = 0; i < 8; ++i) {
        const int e = tid + i * 256;
        const int row = e >> 4;
        const int c4 = e & 15;
        *(float4*)&QP[row * FSTR + c4 * 4] = tf32_rna4(
            *(const float4*)(Qg + (size_t)(q0 + row) * HD + c4 * 4));
    }
    __syncthreads();

    // Q fragments for all 8 k-chunks (warp-private rows)
    uint32_t qf[8][4];
    #pragma unroll
    for (int kc = 0; kc < 8; ++kc) {
        const float* p = &QP[(wid * 16 + g) * FSTR + kc * 8 + t4];
        qf[kc][0] = __float_as_uint(p[0]);
        qf[kc][1] = __float_as_uint(p[8 * FSTR]);
        qf[kc][2] = __float_as_uint(p[4]);
        qf[kc][3] = __float_as_uint(p[8 * FSTR + 4]);
    }

    float oacc[8][4] = {};
    float mr0 = -1e30f, mr1 = -1e30f, l0 = 0.0f, l1 = 0.0f;
    const float scale = 0.125f;

    for (int kt = 0; kt < SS / 64; ++kt) {
        __syncthreads();    // K/V (and first-iter Q frag reads) safe to overwrite

        // Stage K,V tiles [64][64] (rounded to tf32)
        #pragma unroll
        for (int i = 0; i < 4; ++i) {
            const int e = tid + i * 256;
            const int row = e >> 4;
            const int c4 = e & 15;
            const size_t gi = (size_t)(kt * 64 + row) * HD + c4 * 4;
            *(float4*)&Ks[row * FSTR + c4 * 4] =
                tf32_rna4(*(const float4*)(Kg + gi));
            *(float4*)&Vs[row * FSTR + c4 * 4] =
                tf32_rna4(*(const float4*)(Vg + gi));
        }
        __syncthreads();

        // S = Q . K^T : warp computes 16x64 scores
        float sacc[8][4] = {};
        #pragma unroll
        for (int kc = 0; kc < 8; ++kc) {
            #pragma unroll
            for (int nt = 0; nt < 8; ++nt) {
                const float* p = &Ks[(nt * 8 + g) * FSTR + kc * 8 + t4];
                uint32_t bfr[2];
                bfr[0] = __float_as_uint(p[0]);
                bfr[1] = __float_as_uint(p[4]);
                mma_tf32(sacc[nt], qf[kc], bfr);
            }
        }

        // Online softmax. Row g: regs [0],[1]; row g+8: regs [2],[3].
        float mx0 = -1e30f, mx1 = -1e30f;
        #pragma unroll
        for (int nt = 0; nt < 8; ++nt) {
            sacc[nt][0] *= scale; sacc[nt][1] *= scale;
            sacc[nt][2] *= scale; sacc[nt][3] *= scale;
            mx0 = fmaxf(mx0, fmaxf(sacc[nt][0], sacc[nt][1]));
            mx1 = fmaxf(mx1, fmaxf(sacc[nt][2], sacc[nt][3]));
        }
        mx0 = fmaxf(mx0, __shfl_xor_sync(0xffffffffu, mx0, 1));
        mx0 = fmaxf(mx0, __shfl_xor_sync(0xffffffffu, mx0, 2));
        mx1 = fmaxf(mx1, __shfl_xor_sync(0xffffffffu, mx1, 1));
        mx1 = fmaxf(mx1, __shfl_xor_sync(0xffffffffu, mx1, 2));

        const float mn0 = fmaxf(mr0, mx0);
        const float mn1 = fmaxf(mr1, mx1);
        const float corr0 = __expf(mr0 - mn0);
        const float corr1 = __expf(mr1 - mn1);
        mr0 = mn0; mr1 = mn1;

        float rs0 = 0.0f, rs1 = 0.0f;
        #pragma unroll
        for (int nt = 0; nt < 8; ++nt) {
            sacc[nt][0] = __expf(sacc[nt][0] - mn0);
            sacc[nt][1] = __expf(sacc[nt][1] - mn0);
            sacc[nt][2] = __expf(sacc[nt][2] - mn1);
            sacc[nt][3] = __expf(sacc[nt][3] - mn1);
            rs0 += sacc[nt][0] + sacc[nt][1];
            rs1 += sacc[nt][2] + sacc[nt][3];
        }
        rs0 += __shfl_xor_sync(0xffffffffu, rs0, 1);
        rs0 += __shfl_xor_sync(0xffffffffu, rs0, 2);
        rs1 += __shfl_xor_sync(0xffffffffu, rs1, 1);
        rs1 += __shfl_xor_sync(0xffffffffu, rs1, 2);

        l0 = l0 * corr0 + rs0;
        l1 = l1 * corr1 + rs1;

        #pragma unroll
        for (int nt = 0; nt < 8; ++nt) {
            oacc[nt][0] *= corr0; oacc[nt][1] *= corr0;
            oacc[nt][2] *= corr1; oacc[nt][3] *= corr1;
        }

        // P -> smem (warp-private rows; QP reused), rounded to tf32
        __syncwarp();
        {
            const int row = wid * 16 + g;
            #pragma unroll
            for (int nt = 0; nt < 8; ++nt) {
                const int col = nt * 8 + t4 * 2;
                QP[row * FSTR + col]           = tf32_rna(sacc[nt][0]);
                QP[row * FSTR + col + 1]       = tf32_rna(sacc[nt][1]);
                QP[(row + 8) * FSTR + col]     = tf32_rna(sacc[nt][2]);
                QP[(row + 8) * FSTR + col + 1] = tf32_rna(sacc[nt][3]);
            }
        }
        __syncwarp();

        // O += P . V
        #pragma unroll
        for (int kc = 0; kc < 8; ++kc) {
            uint32_t af[4];
            const float* p = &QP[(wid * 16 + g) * FSTR + kc * 8 + t4];
            af[0] = __float_as_uint(p[0]);
            af[1] = __float_as_uint(p[8 * FSTR]);
            af[2] = __float_as_uint(p[4]);
            af[3] = __float_as_uint(p[8 * FSTR + 4]);
            #pragma unroll
            for (int nt = 0; nt < 8; ++nt) {
                const float* vp = &Vs[(kc * 8 + t4) * FSTR + nt * 8 + g];
                uint32_t bfr[2];
                bfr[0] = __float_as_uint(vp[0]);
                bfr[1] = __float_as_uint(vp[4 * FSTR]);
                mma_tf32(oacc[nt], af, bfr);
            }
        }
    }

    // Epilogue: normalize, write [B,S,H*hd]
    const float inv0 = 1.0f / l0;
    const float inv1 = 1.0f / l1;
    const int row0 = q0 + wid * 16 + g;
    const int row1 = row0 + 8;
    #pragma unroll
    for (int nt = 0; nt < 8; ++nt) {
        const int col = h * HD + nt * 8 + t4 * 2;
        float* o0 = &g_attn[((size_t)b * SS + row0) * DD + col];
        float* o1 = &g_attn[((size_t)b * SS + row1) * DD + col];
        o0[0] = oacc[nt][0] * inv0; o0[1] = oacc[nt][1] * inv0;
        o1[0] = oacc[nt][2] * inv1; o1[1] = oacc[nt][3] * inv1;
    }
}

// ---------------------------------------------------------------------------
// Launch
// ---------------------------------------------------------------------------
extern "C" void kernel_launch(void* const* d_in, const int* in_sizes, int n_in,
                              void* d_out, int out_size)
{
    (void)in_sizes; (void)n_in; (void)out_size;
    const float* x      = (const float*)d_in[0];
    const float* w_qkv  = (const float*)d_in[1];
    const float* b_qkv  = (const float*)d_in[2];
    const float* w_proj = (const float*)d_in[3];
    const float* b_proj = (const float*)d_in[4];
    float* out = (float*)d_out;

    cudaFuncSetAttribute(flash_attn_kernel,
                         cudaFuncAttributeMaxDynamicSharedMemorySize,
                         FLASH_SMEM);

    float* attn_ptr = nullptr;
    cudaGetSymbolAddress((void**)&attn_ptr, g_attn);

    // 1) QKV projection: M=4096, N=3072 -> grid (24, 32)
    tc_gemm_kernel<0><<<dim3(3 * DD / 128, BB * SS / 128), 256>>>(
        x, w_qkv, b_qkv, nullptr);

    // 2) Flash attention: grid (16, 32)
    flash_attn_kernel<<<dim3(SS / 128, BB * HH), 256, FLASH_SMEM>>>();

    // 3) Output projection: M=4096, N=1024 -> grid (8, 32)
    tc_gemm_kernel<1><<<dim3(DD / 128, BB * SS / 128), 256>>>(
        attn_ptr, w_proj, b_proj, out);
}